// round 12
// baseline (speedup 1.0000x reference)
#include <cuda_runtime.h>
#include <cuda_bf16.h>
#include <cstdint>

#define S 2048
#define C 4096
#define K 4
#define ND 9            // offsets d=-4..4
#define KKB 36          // K*ND per precision part
#define TM 128          // samples per CTA
#define TN 128          // channels per CTA
#define NKS 7           // k-steps of 16 (K=112 >= 108)
#define QSTR 60         // b32 (k-pair) stride per row: bank-conflict-free
#define SMEM_BYTES (2 * TM * QSTR * 4)   // A + B packed tiles = 61440

static __device__ __forceinline__ void mma16816(float c[4], const uint32_t a[4],
                                                uint32_t b0, uint32_t b1) {
    asm volatile(
        "mma.sync.aligned.m16n8k16.row.col.f32.bf16.bf16.f32 "
        "{%0,%1,%2,%3}, {%4,%5,%6,%7}, {%8,%9}, {%0,%1,%2,%3};"
        : "+f"(c[0]), "+f"(c[1]), "+f"(c[2]), "+f"(c[3])
        : "r"(a[0]), "r"(a[1]), "r"(a[2]), "r"(a[3]), "r"(b0), "r"(b1));
}

// out(S,C) = A(S,108) * B(108,C); A'=[Ahi|Ahi|Alo], B'=[Bhi;Blo;Bhi].
// A[s][p*36+k*9+r..+1] = {w0,w1}; B[p*36+k*9+(d+4)][c] = comp[k][c+d] (0 OOB).
__global__ void __launch_bounds__(256, 2)
smf_hmma(const float* __restrict__ comp,      // (K, C)
         const float* __restrict__ contrib,   // (S, K)
         const float* __restrict__ shift,     // (S, K)
         float* __restrict__ out)             // (S, C)
{
    extern __shared__ uint32_t sm[];
    uint32_t* sA = sm;                 // [TM][QSTR] b32 k-pairs
    uint32_t* sB = sm + TM * QSTR;     // [TN][QSTR]

    const int tid   = threadIdx.x;
    const int wid   = tid >> 5;
    const int lane  = tid & 31;
    const int g     = lane >> 2;       // groupID (0..7)
    const int tg    = lane & 3;        // thread-in-group
    const int cN0   = blockIdx.x * TN;
    const int s0    = blockIdx.y * TM;
    const int warpM = wid & 1;         // 2 warps along M
    const int warpN = wid >> 1;        // 4 warps along N

    // ---- zero both packed tiles (61440 B = 3840 float4) ----
    {
        float4 z = make_float4(0.f, 0.f, 0.f, 0.f);
        float4* p = reinterpret_cast<float4*>(sm);
#pragma unroll
        for (int i = 0; i < 15; i++) p[tid + 256 * i] = z;
    }
    __syncthreads();

    // ---- build B: i -> (band kk = i>>7 in 0..35, channel n = i&127) ----
#pragma unroll 1
    for (int i = tid; i < KKB * TN; i += 256) {
        const int kk = i >> 7;
        const int n  = i & 127;
        const int k  = kk / ND;
        const int d  = kk - k * ND - 4;
        const int gc = cN0 + n + d;
        const float v = (gc >= 0 && gc < C) ? __ldg(&comp[k * C + gc]) : 0.f;
        const __nv_bfloat16 vh = __float2bfloat16(v);
        const __nv_bfloat16 vl = __float2bfloat16(v - __bfloat162float(vh));
        __nv_bfloat16* Bh = reinterpret_cast<__nv_bfloat16*>(sB + n * QSTR);
        Bh[kk]           = vh;     // part 0: hi
        Bh[kk + KKB]     = vl;     // part 1: lo
        Bh[kk + 2 * KKB] = vh;     // part 2: hi
    }

    // ---- build A: thread tid<128 handles sample row tid ----
    if (tid < TM) {
        const float4 sh4 = __ldg(reinterpret_cast<const float4*>(shift + (s0 + tid) * K));
        const float4 w4  = __ldg(reinterpret_cast<const float4*>(contrib + (s0 + tid) * K));
        const float shs[4] = {sh4.x, sh4.y, sh4.z, sh4.w};
        const float ws[4]  = {w4.x,  w4.y,  w4.z,  w4.w};
        __nv_bfloat16* Ah = reinterpret_cast<__nv_bfloat16*>(sA + tid * QSTR);
#pragma unroll
        for (int k = 0; k < K; k++) {
            const float m = floorf(shs[k]);
            const float f = shs[k] - m;
            int r = (int)m + 4;                    // shift in [-4,4) -> r in [0,7]
            r = max(0, min(7, r));
            const float w1 = ws[k] * f;
            const float w0 = ws[k] - w1;
            const __nv_bfloat16 w0h = __float2bfloat16(w0);
            const __nv_bfloat16 w1h = __float2bfloat16(w1);
            const __nv_bfloat16 w0l = __float2bfloat16(w0 - __bfloat162float(w0h));
            const __nv_bfloat16 w1l = __float2bfloat16(w1 - __bfloat162float(w1h));
            const int c0 = k * ND + r;
            Ah[c0]                = w0h;  Ah[c0 + 1]           = w1h;   // hi
            Ah[c0 + KKB]          = w0h;  Ah[c0 + KKB + 1]     = w1h;   // hi (x B lo)
            Ah[c0 + 2 * KKB]      = w0l;  Ah[c0 + 2 * KKB + 1] = w1l;   // lo (x B hi)
        }
    }
    __syncthreads();

    // ---- mainloop: 7 ksteps, warp tile 64(M) x 32(N) ----
    float c[4][4][4];
#pragma unroll
    for (int mi = 0; mi < 4; mi++)
#pragma unroll
        for (int nj = 0; nj < 4; nj++)
#pragma unroll
            for (int q = 0; q < 4; q++) c[mi][nj][q] = 0.f;

    const uint32_t* Abase = sA + (warpM * 64 + g) * QSTR + tg;
    const uint32_t* Bbase = sB + (warpN * 32 + g) * QSTR + tg;

#pragma unroll
    for (int ks = 0; ks < NKS; ks++) {
        uint32_t a[4][4];
#pragma unroll
        for (int mi = 0; mi < 4; mi++) {
            const uint32_t* ap = Abase + mi * 16 * QSTR + ks * 8;
            a[mi][0] = ap[0];
            a[mi][1] = ap[8 * QSTR];
            a[mi][2] = ap[4];
            a[mi][3] = ap[8 * QSTR + 4];
        }
#pragma unroll
        for (int nj = 0; nj < 4; nj++) {
            const uint32_t* bp = Bbase + nj * 8 * QSTR + ks * 8;
            const uint32_t b0 = bp[0];
            const uint32_t b1 = bp[4];
#pragma unroll
            for (int mi = 0; mi < 4; mi++)
                mma16816(c[mi][nj], a[mi], b0, b1);
        }
    }

    // ---- epilogue: c0,c1 -> (row, 2 cols), c2,c3 -> (row+8, 2 cols) ----
    {
        const int row0 = s0 + warpM * 64 + g;
        const int col0 = cN0 + warpN * 32 + 2 * tg;
#pragma unroll
        for (int mi = 0; mi < 4; mi++) {
            const int r0 = row0 + 16 * mi;
#pragma unroll
            for (int nj = 0; nj < 4; nj++) {
                const int cc = col0 + 8 * nj;
                float2 v01 = make_float2(c[mi][nj][0], c[mi][nj][1]);
                float2 v23 = make_float2(c[mi][nj][2], c[mi][nj][3]);
                *reinterpret_cast<float2*>(out + (size_t)r0 * C + cc)       = v01;
                *reinterpret_cast<float2*>(out + (size_t)(r0 + 8) * C + cc) = v23;
            }
        }
    }
}

extern "C" void kernel_launch(void* const* d_in, const int* in_sizes, int n_in,
                              void* d_out, int out_size) {
    // metadata order: inputs (unused), components, contributions, shift
    const float* comp    = (const float*)d_in[1];
    const float* contrib = (const float*)d_in[2];
    const float* shift   = (const float*)d_in[3];
    float*       out     = (float*)d_out;

    static bool configured = false;
    if (!configured) {
        cudaFuncSetAttribute(smf_hmma,
                             cudaFuncAttributeMaxDynamicSharedMemorySize, SMEM_BYTES);
        configured = true;
    }

    dim3 grid(C / TN, S / TM);   // (32, 16) = 512 CTAs
    smf_hmma<<<grid, 256, SMEM_BYTES>>>(comp, contrib, shift, out);
}

// round 13
// speedup vs baseline: 1.0017x; 1.0017x over previous
#include <cuda_runtime.h>
#include <cuda_bf16.h>
#include <cstdint>

#define S 2048
#define C 4096
#define K 4
#define ND 9            // offsets d=-4..4
#define KKB 36          // K*ND per precision part
#define TM 128          // samples per CTA
#define TN 128          // channels per CTA
#define NKS 7           // k-steps of 16 (K=112 >= 108)
#define QSTR 60         // b32 (k-pair) stride per row: bank-conflict-free
#define SMEM_BYTES (2 * TM * QSTR * 4)   // A + B packed tiles = 61440

static __device__ __forceinline__ void mma16816(float c[4], const uint32_t a[4],
                                                uint32_t b0, uint32_t b1) {
    asm volatile(
        "mma.sync.aligned.m16n8k16.row.col.f32.bf16.bf16.f32 "
        "{%0,%1,%2,%3}, {%4,%5,%6,%7}, {%8,%9}, {%0,%1,%2,%3};"
        : "+f"(c[0]), "+f"(c[1]), "+f"(c[2]), "+f"(c[3])
        : "r"(a[0]), "r"(a[1]), "r"(a[2]), "r"(a[3]), "r"(b0), "r"(b1));
}

// out(S,C) = A(S,108) * B(108,C); A'=[Ahi|Ahi|Alo], B'=[Bhi;Blo;Bhi].
// A[s][p*36+k*9+r..+1] = {w0,w1}; B[p*36+k*9+(d+4)][c] = comp[k][c+d] (0 OOB).
__global__ void __launch_bounds__(256, 2)
smf_hmma(const float* __restrict__ comp,      // (K, C)
         const float* __restrict__ contrib,   // (S, K)
         const float* __restrict__ shift,     // (S, K)
         float* __restrict__ out)             // (S, C)
{
    extern __shared__ uint32_t sm[];
    uint32_t* sA = sm;                 // [TM][QSTR] b32 k-pairs
    uint32_t* sB = sm + TM * QSTR;     // [TN][QSTR]

    const int tid   = threadIdx.x;
    const int wid   = tid >> 5;
    const int lane  = tid & 31;
    const int g     = lane >> 2;       // groupID (0..7)
    const int tg    = lane & 3;        // thread-in-group
    const int cN0   = blockIdx.x * TN;
    const int s0    = blockIdx.y * TM;
    const int warpM = wid & 1;         // 2 warps along M
    const int warpN = wid >> 1;        // 4 warps along N

    // ---- B build: batch ALL loads first (MLP=18), then convert+store ----
    // Thread covers row n = tid&127, bands kk = 2*it + (tid>>7), it=0..17.
    const int n  = tid & 127;
    const int hi = tid >> 7;
    float v[18];
#pragma unroll
    for (int it = 0; it < 18; it++) {
        const int kk = 2 * it + hi;
        const int k  = kk / ND;                  // strength-reduced by compiler
        const int d  = kk - k * ND - 4;
        const int gc = cN0 + n + d;
        v[it] = (gc >= 0 && gc < C) ? __ldg(&comp[k * C + gc]) : 0.f;
    }
    {
        __nv_bfloat16* Bh = reinterpret_cast<__nv_bfloat16*>(sB + n * QSTR);
        if (hi == 0) {                            // zero pad halves 108..111 (own row)
            sB[n * QSTR + 54] = 0u;
            sB[n * QSTR + 55] = 0u;
        }
#pragma unroll
        for (int it = 0; it < 18; it++) {
            const int kk = 2 * it + hi;
            const __nv_bfloat16 vh = __float2bfloat16(v[it]);
            const __nv_bfloat16 vl = __float2bfloat16(v[it] - __bfloat162float(vh));
            Bh[kk]           = vh;                // part 0: hi
            Bh[kk + KKB]     = vl;                // part 1: lo
            Bh[kk + 2 * KKB] = vh;                // part 2: hi
        }
    }

    // ---- A build: thread tid<128 owns row tid (zero row, then sparse writes) ----
    if (tid < TM) {
        const float4 sh4 = __ldg(reinterpret_cast<const float4*>(shift + (s0 + tid) * K));
        const float4 w4  = __ldg(reinterpret_cast<const float4*>(contrib + (s0 + tid) * K));
        float4* Az = reinterpret_cast<float4*>(sA + tid * QSTR);   // 240B-aligned
#pragma unroll
        for (int i = 0; i < QSTR / 4; i++) Az[i] = make_float4(0.f, 0.f, 0.f, 0.f);

        const float shs[4] = {sh4.x, sh4.y, sh4.z, sh4.w};
        const float ws[4]  = {w4.x,  w4.y,  w4.z,  w4.w};
        __nv_bfloat16* Ah = reinterpret_cast<__nv_bfloat16*>(sA + tid * QSTR);
#pragma unroll
        for (int k = 0; k < K; k++) {
            const float m = floorf(shs[k]);
            const float f = shs[k] - m;
            int r = (int)m + 4;                    // shift in [-4,4) -> r in [0,7]
            r = max(0, min(7, r));
            const float w1 = ws[k] * f;
            const float w0 = ws[k] - w1;
            const __nv_bfloat16 w0h = __float2bfloat16(w0);
            const __nv_bfloat16 w1h = __float2bfloat16(w1);
            const __nv_bfloat16 w0l = __float2bfloat16(w0 - __bfloat162float(w0h));
            const __nv_bfloat16 w1l = __float2bfloat16(w1 - __bfloat162float(w1h));
            const int c0 = k * ND + r;
            Ah[c0]                = w0h;  Ah[c0 + 1]           = w1h;   // hi
            Ah[c0 + KKB]          = w0h;  Ah[c0 + KKB + 1]     = w1h;   // hi (x B lo)
            Ah[c0 + 2 * KKB]      = w0l;  Ah[c0 + 2 * KKB + 1] = w1l;   // lo (x B hi)
        }
    }
    __syncthreads();

    // ---- mainloop: 7 ksteps, warp tile 64(M) x 32(N) ----
    float c[4][4][4];
#pragma unroll
    for (int mi = 0; mi < 4; mi++)
#pragma unroll
        for (int nj = 0; nj < 4; nj++)
#pragma unroll
            for (int q = 0; q < 4; q++) c[mi][nj][q] = 0.f;

    const uint32_t* Abase = sA + (warpM * 64 + g) * QSTR + tg;
    const uint32_t* Bbase = sB + (warpN * 32 + g) * QSTR + tg;

#pragma unroll
    for (int ks = 0; ks < NKS; ks++) {
        uint32_t a[4][4];
#pragma unroll
        for (int mi = 0; mi < 4; mi++) {
            const uint32_t* ap = Abase + mi * 16 * QSTR + ks * 8;
            a[mi][0] = ap[0];
            a[mi][1] = ap[8 * QSTR];
            a[mi][2] = ap[4];
            a[mi][3] = ap[8 * QSTR + 4];
        }
#pragma unroll
        for (int nj = 0; nj < 4; nj++) {
            const uint32_t* bp = Bbase + nj * 8 * QSTR + ks * 8;
            const uint32_t b0 = bp[0];
            const uint32_t b1 = bp[4];
#pragma unroll
            for (int mi = 0; mi < 4; mi++)
                mma16816(c[mi][nj], a[mi], b0, b1);
        }
    }

    // ---- epilogue: c0,c1 -> (row, 2 cols), c2,c3 -> (row+8, 2 cols) ----
    {
        const int row0 = s0 + warpM * 64 + g;
        const int col0 = cN0 + warpN * 32 + 2 * tg;
#pragma unroll
        for (int mi = 0; mi < 4; mi++) {
            const int r0 = row0 + 16 * mi;
#pragma unroll
            for (int nj = 0; nj < 4; nj++) {
                const int cc = col0 + 8 * nj;
                float2 v01 = make_float2(c[mi][nj][0], c[mi][nj][1]);
                float2 v23 = make_float2(c[mi][nj][2], c[mi][nj][3]);
                *reinterpret_cast<float2*>(out + (size_t)r0 * C + cc)       = v01;
                *reinterpret_cast<float2*>(out + (size_t)(r0 + 8) * C + cc) = v23;
            }
        }
    }
}

extern "C" void kernel_launch(void* const* d_in, const int* in_sizes, int n_in,
                              void* d_out, int out_size) {
    // metadata order: inputs (unused), components, contributions, shift
    const float* comp    = (const float*)d_in[1];
    const float* contrib = (const float*)d_in[2];
    const float* shift   = (const float*)d_in[3];
    float*       out     = (float*)d_out;

    static bool configured = false;
    if (!configured) {
        cudaFuncSetAttribute(smf_hmma,
                             cudaFuncAttributeMaxDynamicSharedMemorySize, SMEM_BYTES);
        configured = true;
    }

    dim3 grid(C / TN, S / TM);   // (32, 16) = 512 CTAs
    smf_hmma<<<grid, 256, SMEM_BYTES>>>(comp, contrib, shift, out);
}